// round 1
// baseline (speedup 1.0000x reference)
#include <cuda_runtime.h>

#define GG 256
#define NN 512
#define KK 6
#define FF 64
#define TT (GG*NN)

// scratch (static device arrays: no allocation allowed)
__device__ int   g_idx[TT*KK];
__device__ float g_hA[TT*FF];
__device__ float g_hB[TT*FF];
__device__ float g_part[(TT/128)*FF];   // per-128-row-block pooled partials

#define KNN_SMEM   ((NN*FF + NN) * 4)
#define LIN12_SMEM ((128*64 + 2*64*64 + 256) * 4)
#define GCONV_SMEM ((128*64 + 64*64 + 64) * 4)
#define LIN34_SMEM ((128*64 + 2*64*64 + 16*64 + 256) * 4)

// ---------------------------------------------------------------------------
// kNN: one block per graph. Whole graph (512x64 f32 = 128KB) in smem.
// 256 threads, 2 queries each (query rows register-resident).
// d(i,j) = (sq_i + sq_j) - 2*dot, self excluded, keep 6 smallest,
// strict '<' insertion => stable tie-break (earlier index wins), matching top_k.
// ---------------------------------------------------------------------------
__global__ void __launch_bounds__(256, 1) knn_kernel(const float* __restrict__ x)
{
    extern __shared__ float sm[];
    float* xs = sm;              // 512*64
    float* sq = sm + NN*FF;      // 512
    const int g   = blockIdx.x;
    const int tid = threadIdx.x;
    float4* xs4 = (float4*)xs;
    const float4* xg4 = (const float4*)(x + (size_t)g * NN * FF);

    for (int i = tid; i < NN*FF/4; i += 256) xs4[i] = xg4[i];
    __syncthreads();

    for (int r = tid; r < NN; r += 256) {
        const float4* row = xs4 + r*16;
        float s = 0.f;
        #pragma unroll
        for (int k2 = 0; k2 < 16; k2++) {
            float4 v = row[k2];
            s += v.x*v.x + v.y*v.y + v.z*v.z + v.w*v.w;
        }
        sq[r] = s;
    }
    __syncthreads();

    const int q0 = tid, q1 = tid + 256;
    float4 xq0[16], xq1[16];
    #pragma unroll
    for (int k2 = 0; k2 < 16; k2++) { xq0[k2] = xs4[q0*16 + k2]; xq1[k2] = xs4[q1*16 + k2]; }
    const float sq0 = sq[q0], sq1 = sq[q1];

    float bd0[6], bd1[6];
    int   bi0[6], bi1[6];
    #pragma unroll
    for (int t = 0; t < 6; t++) { bd0[t] = 3.0e38f; bd1[t] = 3.0e38f; bi0[t] = 0; bi1[t] = 0; }
    float w0v = 3.0e38f, w1v = 3.0e38f;
    int   w0s = 0,       w1s = 0;

    for (int j = 0; j < NN; j++) {
        float a0 = 0.f, a1 = 0.f, a2 = 0.f, a3 = 0.f;
        #pragma unroll
        for (int k2 = 0; k2 < 16; k2 += 2) {
            float4 v0 = xs4[j*16 + k2];
            float4 v1 = xs4[j*16 + k2 + 1];
            a0 = fmaf(xq0[k2].x,   v0.x, a0); a0 = fmaf(xq0[k2].y,   v0.y, a0);
            a0 = fmaf(xq0[k2].z,   v0.z, a0); a0 = fmaf(xq0[k2].w,   v0.w, a0);
            a2 = fmaf(xq0[k2+1].x, v1.x, a2); a2 = fmaf(xq0[k2+1].y, v1.y, a2);
            a2 = fmaf(xq0[k2+1].z, v1.z, a2); a2 = fmaf(xq0[k2+1].w, v1.w, a2);
            a1 = fmaf(xq1[k2].x,   v0.x, a1); a1 = fmaf(xq1[k2].y,   v0.y, a1);
            a1 = fmaf(xq1[k2].z,   v0.z, a1); a1 = fmaf(xq1[k2].w,   v0.w, a1);
            a3 = fmaf(xq1[k2+1].x, v1.x, a3); a3 = fmaf(xq1[k2+1].y, v1.y, a3);
            a3 = fmaf(xq1[k2+1].z, v1.z, a3); a3 = fmaf(xq1[k2+1].w, v1.w, a3);
        }
        const float dot0 = a0 + a2;
        const float dot1 = a1 + a3;
        const float sj = sq[j];
        const float d0 = __fsub_rn(sq0 + sj, __fmul_rn(2.f, dot0));
        const float d1 = __fsub_rn(sq1 + sj, __fmul_rn(2.f, dot1));

        if (j != q0 && d0 < w0v) {
            bd0[w0s] = d0; bi0[w0s] = j;
            w0v = bd0[0]; w0s = 0;
            #pragma unroll
            for (int t = 1; t < 6; t++) if (bd0[t] > w0v) { w0v = bd0[t]; w0s = t; }
        }
        if (j != q1 && d1 < w1v) {
            bd1[w1s] = d1; bi1[w1s] = j;
            w1v = bd1[0]; w1s = 0;
            #pragma unroll
            for (int t = 1; t < 6; t++) if (bd1[t] > w1v) { w1v = bd1[t]; w1s = t; }
        }
    }

    const int base = g * NN;
    #pragma unroll
    for (int t = 0; t < 6; t++) {
        g_idx[(size_t)(base + q0)*KK + t] = base + bi0[t];
        g_idx[(size_t)(base + q1)*KK + t] = base + bi1[t];
    }
}

// ---------------------------------------------------------------------------
// 128-row x 64-col tile matmul from smem. 256 threads; each thread: 8 rows x 4 cols.
// ---------------------------------------------------------------------------
__device__ __forceinline__ void mm_tile(const float* __restrict__ xs,
                                        const float* __restrict__ Ws,
                                        float acc[8][4], int rg, int cg)
{
    #pragma unroll
    for (int r = 0; r < 8; r++) { acc[r][0]=0.f; acc[r][1]=0.f; acc[r][2]=0.f; acc[r][3]=0.f; }
    #pragma unroll 1
    for (int k = 0; k < 64; k += 4) {
        const float4 w0 = *(const float4*)&Ws[(k+0)*64 + cg];
        const float4 w1 = *(const float4*)&Ws[(k+1)*64 + cg];
        const float4 w2 = *(const float4*)&Ws[(k+2)*64 + cg];
        const float4 w3 = *(const float4*)&Ws[(k+3)*64 + cg];
        #pragma unroll
        for (int r = 0; r < 8; r++) {
            const float4 xv = *(const float4*)&xs[(rg*8 + r)*64 + k];
            acc[r][0] = fmaf(xv.x, w0.x, acc[r][0]); acc[r][0] = fmaf(xv.y, w1.x, acc[r][0]);
            acc[r][0] = fmaf(xv.z, w2.x, acc[r][0]); acc[r][0] = fmaf(xv.w, w3.x, acc[r][0]);
            acc[r][1] = fmaf(xv.x, w0.y, acc[r][1]); acc[r][1] = fmaf(xv.y, w1.y, acc[r][1]);
            acc[r][1] = fmaf(xv.z, w2.y, acc[r][1]); acc[r][1] = fmaf(xv.w, w3.y, acc[r][1]);
            acc[r][2] = fmaf(xv.x, w0.z, acc[r][2]); acc[r][2] = fmaf(xv.y, w1.z, acc[r][2]);
            acc[r][2] = fmaf(xv.z, w2.z, acc[r][2]); acc[r][2] = fmaf(xv.w, w3.z, acc[r][2]);
            acc[r][3] = fmaf(xv.x, w0.w, acc[r][3]); acc[r][3] = fmaf(xv.y, w1.w, acc[r][3]);
            acc[r][3] = fmaf(xv.z, w2.w, acc[r][3]); acc[r][3] = fmaf(xv.w, w3.w, acc[r][3]);
        }
    }
}

// ---------------------------------------------------------------------------
// Fused prelu(x@W1+b1) -> prelu(.@W2+b2). 1024 blocks x 256 thr, 128 rows/block.
// ---------------------------------------------------------------------------
__global__ void __launch_bounds__(256) lin12_kernel(
    const float* __restrict__ x,
    const float* __restrict__ W1, const float* __restrict__ b1, const float* __restrict__ a1,
    const float* __restrict__ W2, const float* __restrict__ b2, const float* __restrict__ a2,
    float* __restrict__ out)
{
    extern __shared__ float sm[];
    float* xs = sm;             // 8192
    float* Ws = sm + 8192;      // 8192 (W1 | W2)
    float* bs = sm + 16384;     // 256 (b1,a1,b2,a2)
    const int tid = threadIdx.x;
    const size_t rowbase = (size_t)blockIdx.x * 128;

    float4* xs4 = (float4*)xs;
    const float4* xin = (const float4*)(x + rowbase * FF);
    for (int i = tid; i < 2048; i += 256) xs4[i] = xin[i];
    float4* Ws4 = (float4*)Ws;
    for (int i = tid; i < 1024; i += 256) {
        Ws4[i]        = ((const float4*)W1)[i];
        Ws4[1024 + i] = ((const float4*)W2)[i];
    }
    if (tid < 64) { bs[tid] = b1[tid]; bs[64+tid] = a1[tid]; bs[128+tid] = b2[tid]; bs[192+tid] = a2[tid]; }
    __syncthreads();

    const int rg = tid >> 4, cg = (tid & 15) * 4;
    float acc[8][4];
    mm_tile(xs, Ws, acc, rg, cg);
    __syncthreads();
    #pragma unroll
    for (int r = 0; r < 8; r++)
        #pragma unroll
        for (int c = 0; c < 4; c++) {
            float v = acc[r][c] + bs[cg + c];
            v = (v >= 0.f) ? v : v * bs[64 + cg + c];
            xs[(rg*8 + r)*64 + cg + c] = v;
        }
    __syncthreads();
    mm_tile(xs, Ws + 4096, acc, rg, cg);
    #pragma unroll
    for (int r = 0; r < 8; r++) {
        float4 o;
        float v;
        v = acc[r][0] + bs[128+cg+0]; o.x = (v >= 0.f) ? v : v * bs[192+cg+0];
        v = acc[r][1] + bs[128+cg+1]; o.y = (v >= 0.f) ? v : v * bs[192+cg+1];
        v = acc[r][2] + bs[128+cg+2]; o.z = (v >= 0.f) ? v : v * bs[192+cg+2];
        v = acc[r][3] + bs[128+cg+3]; o.w = (v >= 0.f) ? v : v * bs[192+cg+3];
        *(float4*)&out[(rowbase + rg*8 + r)*FF + cg] = o;
    }
}

// ---------------------------------------------------------------------------
// GeneralConv: out[i] = (sum_{j in nbr(i)} h[j]) @ W + 6*b + h[i]
// ---------------------------------------------------------------------------
__global__ void __launch_bounds__(256) gconv_kernel(
    const float* __restrict__ hin,
    const float* __restrict__ Wc, const float* __restrict__ bc,
    float* __restrict__ out)
{
    extern __shared__ float sm[];
    float* ss = sm;             // 8192 (gathered neighbor sums)
    float* Ws = sm + 8192;      // 4096
    float* bs = sm + 12288;     // 64
    const int tid = threadIdx.x;
    const size_t rowbase = (size_t)blockIdx.x * 128;

    float4* Ws4 = (float4*)Ws;
    for (int i = tid; i < 1024; i += 256) Ws4[i] = ((const float4*)Wc)[i];
    if (tid < 64) bs[tid] = bc[tid];

    {   // gather-sum: 2 threads per row (32 feats each)
        const int r = tid >> 1;
        const int half = (tid & 1) * 8;     // float4 chunk offset
        const int* ip = g_idx + ((size_t)rowbase + r) * KK;
        float4 acc4[8];
        #pragma unroll
        for (int c = 0; c < 8; c++) acc4[c] = make_float4(0.f, 0.f, 0.f, 0.f);
        #pragma unroll
        for (int j = 0; j < KK; j++) {
            const float4* nb = (const float4*)(hin + (size_t)ip[j] * FF) + half;
            #pragma unroll
            for (int c = 0; c < 8; c++) {
                float4 v = nb[c];
                acc4[c].x += v.x; acc4[c].y += v.y; acc4[c].z += v.z; acc4[c].w += v.w;
            }
        }
        float4* ss4 = (float4*)ss;
        #pragma unroll
        for (int c = 0; c < 8; c++) ss4[r*16 + half + c] = acc4[c];
    }
    __syncthreads();

    const int rg = tid >> 4, cg = (tid & 15) * 4;
    float acc[8][4];
    mm_tile(ss, Ws, acc, rg, cg);
    #pragma unroll
    for (int r = 0; r < 8; r++) {
        const size_t row = rowbase + rg*8 + r;
        const float4 hv = *(const float4*)&hin[row*FF + cg];
        float4 o;
        o.x = acc[r][0] + 6.f*bs[cg+0] + hv.x;
        o.y = acc[r][1] + 6.f*bs[cg+1] + hv.y;
        o.z = acc[r][2] + 6.f*bs[cg+2] + hv.z;
        o.w = acc[r][3] + 6.f*bs[cg+3] + hv.w;
        *(float4*)&out[row*FF + cg] = o;
    }
}

// ---------------------------------------------------------------------------
// Fused prelu(.@W3+b3) -> prelu(.@W4+b4) -> per-block column partial sums (pool)
// ---------------------------------------------------------------------------
__global__ void __launch_bounds__(256) lin34_pool_kernel(
    const float* __restrict__ hin,
    const float* __restrict__ W3, const float* __restrict__ b3, const float* __restrict__ a3,
    const float* __restrict__ W4, const float* __restrict__ b4, const float* __restrict__ a4)
{
    extern __shared__ float sm[];
    float* xs = sm;             // 8192
    float* Ws = sm + 8192;      // 8192
    float* ps = sm + 16384;     // 1024
    float* bs = sm + 17408;     // 256
    const int tid = threadIdx.x;
    const size_t rowbase = (size_t)blockIdx.x * 128;

    float4* xs4 = (float4*)xs;
    const float4* xin = (const float4*)(hin + rowbase * FF);
    for (int i = tid; i < 2048; i += 256) xs4[i] = xin[i];
    float4* Ws4 = (float4*)Ws;
    for (int i = tid; i < 1024; i += 256) {
        Ws4[i]        = ((const float4*)W3)[i];
        Ws4[1024 + i] = ((const float4*)W4)[i];
    }
    if (tid < 64) { bs[tid] = b3[tid]; bs[64+tid] = a3[tid]; bs[128+tid] = b4[tid]; bs[192+tid] = a4[tid]; }
    __syncthreads();

    const int rg = tid >> 4, cg = (tid & 15) * 4;
    float acc[8][4];
    mm_tile(xs, Ws, acc, rg, cg);
    __syncthreads();
    #pragma unroll
    for (int r = 0; r < 8; r++)
        #pragma unroll
        for (int c = 0; c < 4; c++) {
            float v = acc[r][c] + bs[cg + c];
            v = (v >= 0.f) ? v : v * bs[64 + cg + c];
            xs[(rg*8 + r)*64 + cg + c] = v;
        }
    __syncthreads();
    mm_tile(xs, Ws + 4096, acc, rg, cg);

    float cs[4] = {0.f, 0.f, 0.f, 0.f};
    #pragma unroll
    for (int r = 0; r < 8; r++)
        #pragma unroll
        for (int c = 0; c < 4; c++) {
            float v = acc[r][c] + bs[128 + cg + c];
            v = (v >= 0.f) ? v : v * bs[192 + cg + c];
            cs[c] += v;
        }
    #pragma unroll
    for (int c = 0; c < 4; c++) ps[rg*64 + cg + c] = cs[c];
    __syncthreads();

    if (tid < 64) {
        float s = 0.f;
        #pragma unroll
        for (int i = 0; i < 16; i++) s += ps[i*64 + tid];
        g_part[(size_t)blockIdx.x * FF + tid] = s;
    }
}

// ---------------------------------------------------------------------------
// Head MLP: pooled[64] -> 256 -> 256 -> 64 -> 1 (leaky 0.2). One block per graph.
// ---------------------------------------------------------------------------
__global__ void __launch_bounds__(256) head_kernel(
    const float* __restrict__ Wh1, const float* __restrict__ bh1,
    const float* __restrict__ Wh2, const float* __restrict__ bh2,
    const float* __restrict__ Wh3, const float* __restrict__ bh3,
    const float* __restrict__ Wh4, const float* __restrict__ bh4,
    float* __restrict__ out)
{
    __shared__ float p[64], y1[256], y2[256], y3[64];
    const int g = blockIdx.x, t = threadIdx.x;
    if (t < 64) {
        p[t] = g_part[(size_t)(g*4 + 0)*FF + t] + g_part[(size_t)(g*4 + 1)*FF + t]
             + g_part[(size_t)(g*4 + 2)*FF + t] + g_part[(size_t)(g*4 + 3)*FF + t];
    }
    __syncthreads();
    {
        float v = bh1[t];
        #pragma unroll 4
        for (int k = 0; k < 64; k++) v = fmaf(p[k], Wh1[k*256 + t], v);
        y1[t] = (v >= 0.f) ? v : 0.2f * v;
    }
    __syncthreads();
    {
        float v = bh2[t];
        #pragma unroll 4
        for (int k = 0; k < 256; k++) v = fmaf(y1[k], Wh2[k*256 + t], v);
        y2[t] = (v >= 0.f) ? v : 0.2f * v;
    }
    __syncthreads();
    if (t < 64) {
        float v = bh3[t];
        #pragma unroll 4
        for (int k = 0; k < 256; k++) v = fmaf(y2[k], Wh3[k*64 + t], v);
        y3[t] = (v >= 0.f) ? v : 0.2f * v;
    }
    __syncthreads();
    if (t == 0) {
        float v = bh4[0];
        #pragma unroll
        for (int k = 0; k < 64; k++) v = fmaf(y3[k], Wh4[k], v);
        out[g] = v;
    }
}

// ---------------------------------------------------------------------------
extern "C" void kernel_launch(void* const* d_in, const int* in_sizes, int n_in,
                              void* d_out, int out_size)
{
    const float* x   = (const float*)d_in[0];
    const float* W1  = (const float*)d_in[1];
    const float* b1  = (const float*)d_in[2];
    const float* a1  = (const float*)d_in[3];
    const float* W2  = (const float*)d_in[4];
    const float* b2  = (const float*)d_in[5];
    const float* a2  = (const float*)d_in[6];
    const float* Wc1 = (const float*)d_in[7];
    const float* bc1 = (const float*)d_in[8];
    const float* Wc2 = (const float*)d_in[9];
    const float* bc2 = (const float*)d_in[10];
    const float* Wc3 = (const float*)d_in[11];
    const float* bc3 = (const float*)d_in[12];
    const float* Wc4 = (const float*)d_in[13];
    const float* bc4 = (const float*)d_in[14];
    const float* W3  = (const float*)d_in[15];
    const float* b3  = (const float*)d_in[16];
    const float* a3  = (const float*)d_in[17];
    const float* W4  = (const float*)d_in[18];
    const float* b4  = (const float*)d_in[19];
    const float* a4  = (const float*)d_in[20];
    const float* Wh1 = (const float*)d_in[21];
    const float* bh1 = (const float*)d_in[22];
    const float* Wh2 = (const float*)d_in[23];
    const float* bh2 = (const float*)d_in[24];
    const float* Wh3 = (const float*)d_in[25];
    const float* bh3 = (const float*)d_in[26];
    const float* Wh4 = (const float*)d_in[27];
    const float* bh4 = (const float*)d_in[28];
    float* out = (float*)d_out;

    float *hA = nullptr, *hB = nullptr;
    cudaGetSymbolAddress((void**)&hA, g_hA);
    cudaGetSymbolAddress((void**)&hB, g_hB);

    cudaFuncSetAttribute(knn_kernel,       cudaFuncAttributeMaxDynamicSharedMemorySize, KNN_SMEM);
    cudaFuncSetAttribute(lin12_kernel,     cudaFuncAttributeMaxDynamicSharedMemorySize, LIN12_SMEM);
    cudaFuncSetAttribute(gconv_kernel,     cudaFuncAttributeMaxDynamicSharedMemorySize, GCONV_SMEM);
    cudaFuncSetAttribute(lin34_pool_kernel,cudaFuncAttributeMaxDynamicSharedMemorySize, LIN34_SMEM);

    knn_kernel<<<GG, 256, KNN_SMEM>>>(x);
    lin12_kernel<<<TT/128, 256, LIN12_SMEM>>>(x, W1, b1, a1, W2, b2, a2, hA);
    gconv_kernel<<<TT/128, 256, GCONV_SMEM>>>(hA, Wc1, bc1, hB);
    gconv_kernel<<<TT/128, 256, GCONV_SMEM>>>(hB, Wc2, bc2, hA);
    gconv_kernel<<<TT/128, 256, GCONV_SMEM>>>(hA, Wc3, bc3, hB);
    gconv_kernel<<<TT/128, 256, GCONV_SMEM>>>(hB, Wc4, bc4, hA);
    lin34_pool_kernel<<<TT/128, 256, LIN34_SMEM>>>(hA, W3, b3, a3, W4, b4, a4);
    head_kernel<<<GG, 256>>>(Wh1, bh1, Wh2, bh2, Wh3, bh3, Wh4, bh4, out);
}

// round 4
// speedup vs baseline: 1.0382x; 1.0382x over previous
#include <cuda_runtime.h>
#include <cstdint>

#define GG 256
#define NN 512
#define KK 6
#define FF 64
#define TT (GG*NN)

typedef unsigned long long u64;

// scratch (static device arrays: no allocation allowed)
__device__ int   g_idx[TT*KK];
__device__ float g_hA[TT*FF];
__device__ float g_hB[TT*FF];
__device__ float g_part[(TT/128)*FF];   // per-128-row-block pooled partials

#define KNN_SMEM   ((NN*FF + NN) * 4)
#define LIN12_SMEM ((128*64 + 2*64*64 + 256) * 4)
#define GCONV_SMEM ((128*64 + 64*64 + 64) * 4)
#define LIN34_SMEM ((128*64 + 2*64*64 + 16*64 + 256) * 4)

// ---------------------------------------------------------------------------
// packed f32x2 helpers (FFMA2 path — only reachable via PTX)
// ---------------------------------------------------------------------------
__device__ __forceinline__ u64 fma2(u64 a, u64 b, u64 c) {
    u64 d;
    asm("fma.rn.f32x2 %0, %1, %2, %3;" : "=l"(d) : "l"(a), "l"(b), "l"(c));
    return d;
}
__device__ __forceinline__ u64 add2(u64 a, u64 b) {
    u64 d;
    asm("add.rn.f32x2 %0, %1, %2;" : "=l"(d) : "l"(a), "l"(b));
    return d;
}
__device__ __forceinline__ u64 pack2(float lo, float hi) {
    u64 d;
    asm("mov.b64 %0, {%1, %2};" : "=l"(d) : "f"(lo), "f"(hi));
    return d;
}
__device__ __forceinline__ float2 unpack2(u64 v) {
    float lo, hi;
    asm("mov.b64 {%0, %1}, %2;" : "=f"(lo), "=f"(hi) : "l"(v));
    return make_float2(lo, hi);
}

// ---------------------------------------------------------------------------
// kNN: one block per graph. Whole graph (512x64 f32 = 128KB) in smem.
// 256 threads, 2 queries each (query rows register-resident as u64 lane pairs).
// d(i,j) = (sq_i + sq_j) - 2*dot via FFMA2; keep 6 smallest (strict '<').
// ---------------------------------------------------------------------------
__global__ void __launch_bounds__(256, 1) knn_kernel(const float* __restrict__ x)
{
    extern __shared__ float sm[];
    float* xs = sm;              // 512*64
    float* sq = sm + NN*FF;      // 512
    const int g   = blockIdx.x;
    const int tid = threadIdx.x;
    float4* xs4 = (float4*)xs;
    const float4* xg4 = (const float4*)(x + (size_t)g * NN * FF);

    for (int i = tid; i < NN*FF/4; i += 256) xs4[i] = xg4[i];
    __syncthreads();

    for (int r = tid; r < NN; r += 256) {
        const float4* row = xs4 + r*16;
        float s = 0.f;
        #pragma unroll
        for (int k2 = 0; k2 < 16; k2++) {
            float4 v = row[k2];
            s += v.x*v.x + v.y*v.y + v.z*v.z + v.w*v.w;
        }
        sq[r] = s;
    }
    __syncthreads();

    const int q0 = tid, q1 = tid + 256;
    const u64* xsu = (const u64*)xs;
    u64 xq0[32], xq1[32];
    #pragma unroll
    for (int k = 0; k < 32; k++) { xq0[k] = xsu[q0*32 + k]; xq1[k] = xsu[q1*32 + k]; }
    const float sq0 = sq[q0], sq1 = sq[q1];

    float bd0[6], bd1[6];
    int   bi0[6], bi1[6];
    #pragma unroll
    for (int t = 0; t < 6; t++) { bd0[t] = 3.0e38f; bd1[t] = 3.0e38f; bi0[t] = 0; bi1[t] = 0; }
    float w0v = 3.0e38f, w1v = 3.0e38f;
    int   w0s = 0,       w1s = 0;

    for (int j = 0; j < NN; j++) {
        const ulonglong2* cj = (const ulonglong2*)(xs + j*FF);
        u64 a0 = 0ull, b0 = 0ull, a1 = 0ull, b1 = 0ull;
        #pragma unroll
        for (int k = 0; k < 16; k++) {
            const ulonglong2 c = cj[k];
            a0 = fma2(xq0[2*k],   c.x, a0);
            b0 = fma2(xq0[2*k+1], c.y, b0);
            a1 = fma2(xq1[2*k],   c.x, a1);
            b1 = fma2(xq1[2*k+1], c.y, b1);
        }
        const float2 f0 = unpack2(add2(a0, b0));
        const float2 f1 = unpack2(add2(a1, b1));
        const float dot0 = f0.x + f0.y;
        const float dot1 = f1.x + f1.y;
        const float sj = sq[j];
        const float d0 = __fsub_rn(sq0 + sj, __fmul_rn(2.f, dot0));
        const float d1 = __fsub_rn(sq1 + sj, __fmul_rn(2.f, dot1));

        if (j != q0 && d0 < w0v) {
            bd0[w0s] = d0; bi0[w0s] = j;
            w0v = bd0[0]; w0s = 0;
            #pragma unroll
            for (int t = 1; t < 6; t++) if (bd0[t] > w0v) { w0v = bd0[t]; w0s = t; }
        }
        if (j != q1 && d1 < w1v) {
            bd1[w1s] = d1; bi1[w1s] = j;
            w1v = bd1[0]; w1s = 0;
            #pragma unroll
            for (int t = 1; t < 6; t++) if (bd1[t] > w1v) { w1v = bd1[t]; w1s = t; }
        }
    }

    const int base = g * NN;
    #pragma unroll
    for (int t = 0; t < 6; t++) {
        g_idx[(size_t)(base + q0)*KK + t] = base + bi0[t];
        g_idx[(size_t)(base + q1)*KK + t] = base + bi1[t];
    }
}

// ---------------------------------------------------------------------------
// 128-row x 64-col tile matmul from smem, FFMA2 over column pairs.
// 256 threads; each thread: 8 rows x 4 cols (2 u64 col-pairs per row).
// Accumulation order per output element identical to scalar k,k+1,k+2,k+3.
// ---------------------------------------------------------------------------
__device__ __forceinline__ void mm_tile2(const float* __restrict__ xs,
                                         const float* __restrict__ Ws,
                                         u64 acc2[8][2], int rg, int cg)
{
    #pragma unroll
    for (int r = 0; r < 8; r++) { acc2[r][0] = 0ull; acc2[r][1] = 0ull; }
    #pragma unroll 2
    for (int k = 0; k < 64; k += 4) {
        const ulonglong2 w0 = *(const ulonglong2*)&Ws[(k+0)*64 + cg];
        const ulonglong2 w1 = *(const ulonglong2*)&Ws[(k+1)*64 + cg];
        const ulonglong2 w2 = *(const ulonglong2*)&Ws[(k+2)*64 + cg];
        const ulonglong2 w3 = *(const ulonglong2*)&Ws[(k+3)*64 + cg];
        #pragma unroll
        for (int r = 0; r < 8; r++) {
            const float4 xv = *(const float4*)&xs[(rg*8 + r)*64 + k];
            const u64 x0 = pack2(xv.x, xv.x);
            const u64 x1 = pack2(xv.y, xv.y);
            const u64 x2 = pack2(xv.z, xv.z);
            const u64 x3 = pack2(xv.w, xv.w);
            acc2[r][0] = fma2(x0, w0.x, acc2[r][0]);
            acc2[r][1] = fma2(x0, w0.y, acc2[r][1]);
            acc2[r][0] = fma2(x1, w1.x, acc2[r][0]);
            acc2[r][1] = fma2(x1, w1.y, acc2[r][1]);
            acc2[r][0] = fma2(x2, w2.x, acc2[r][0]);
            acc2[r][1] = fma2(x2, w2.y, acc2[r][1]);
            acc2[r][0] = fma2(x3, w3.x, acc2[r][0]);
            acc2[r][1] = fma2(x3, w3.y, acc2[r][1]);
        }
    }
}

// ---------------------------------------------------------------------------
// Fused prelu(x@W1+b1) -> prelu(.@W2+b2). 1024 blocks x 256 thr, 128 rows/block.
// ---------------------------------------------------------------------------
__global__ void __launch_bounds__(256) lin12_kernel(
    const float* __restrict__ x,
    const float* __restrict__ W1, const float* __restrict__ b1, const float* __restrict__ a1,
    const float* __restrict__ W2, const float* __restrict__ b2, const float* __restrict__ a2,
    float* __restrict__ out)
{
    extern __shared__ float smf[];
    float* xs = smf;             // 8192
    float* Ws = smf + 8192;      // 8192 (W1 | W2)
    float* bs = smf + 16384;     // 256 (b1,a1,b2,a2)
    const int tid = threadIdx.x;
    const size_t rowbase = (size_t)blockIdx.x * 128;

    float4* xs4 = (float4*)xs;
    const float4* xin = (const float4*)(x + rowbase * FF);
    for (int i = tid; i < 2048; i += 256) xs4[i] = xin[i];
    float4* Ws4 = (float4*)Ws;
    for (int i = tid; i < 1024; i += 256) {
        Ws4[i]        = ((const float4*)W1)[i];
        Ws4[1024 + i] = ((const float4*)W2)[i];
    }
    if (tid < 64) { bs[tid] = b1[tid]; bs[64+tid] = a1[tid]; bs[128+tid] = b2[tid]; bs[192+tid] = a2[tid]; }
    __syncthreads();

    const int rg = tid >> 4, cg = (tid & 15) * 4;
    u64 acc2[8][2];
    mm_tile2(xs, Ws, acc2, rg, cg);
    __syncthreads();
    #pragma unroll
    for (int r = 0; r < 8; r++) {
        const float2 p0 = unpack2(acc2[r][0]);
        const float2 p1 = unpack2(acc2[r][1]);
        const float a4[4] = {p0.x, p0.y, p1.x, p1.y};
        #pragma unroll
        for (int c = 0; c < 4; c++) {
            float v = a4[c] + bs[cg + c];
            v = (v >= 0.f) ? v : v * bs[64 + cg + c];
            xs[(rg*8 + r)*64 + cg + c] = v;
        }
    }
    __syncthreads();
    mm_tile2(xs, Ws + 4096, acc2, rg, cg);
    #pragma unroll
    for (int r = 0; r < 8; r++) {
        const float2 p0 = unpack2(acc2[r][0]);
        const float2 p1 = unpack2(acc2[r][1]);
        float4 o;
        float v;
        v = p0.x + bs[128+cg+0]; o.x = (v >= 0.f) ? v : v * bs[192+cg+0];
        v = p0.y + bs[128+cg+1]; o.y = (v >= 0.f) ? v : v * bs[192+cg+1];
        v = p1.x + bs[128+cg+2]; o.z = (v >= 0.f) ? v : v * bs[192+cg+2];
        v = p1.y + bs[128+cg+3]; o.w = (v >= 0.f) ? v : v * bs[192+cg+3];
        *(float4*)&out[(rowbase + rg*8 + r)*FF + cg] = o;
    }
}

// ---------------------------------------------------------------------------
// GeneralConv: out[i] = (sum_{j in nbr(i)} h[j]) @ W + 6*b + h[i]
// ---------------------------------------------------------------------------
__global__ void __launch_bounds__(256) gconv_kernel(
    const float* __restrict__ hin,
    const float* __restrict__ Wc, const float* __restrict__ bc,
    float* __restrict__ out)
{
    extern __shared__ float smf[];
    float* ss = smf;             // 8192 (gathered neighbor sums)
    float* Ws = smf + 8192;      // 4096
    float* bs = smf + 12288;     // 64
    const int tid = threadIdx.x;
    const size_t rowbase = (size_t)blockIdx.x * 128;

    float4* Ws4 = (float4*)Ws;
    for (int i = tid; i < 1024; i += 256) Ws4[i] = ((const float4*)Wc)[i];
    if (tid < 64) bs[tid] = bc[tid];

    {   // gather-sum: 2 threads per row (32 feats each)
        const int r = tid >> 1;
        const int half = (tid & 1) * 8;     // float4 chunk offset
        const int* ip = g_idx + ((size_t)rowbase + r) * KK;
        float4 acc4[8];
        #pragma unroll
        for (int c = 0; c < 8; c++) acc4[c] = make_float4(0.f, 0.f, 0.f, 0.f);
        #pragma unroll
        for (int j = 0; j < KK; j++) {
            const float4* nb = (const float4*)(hin + (size_t)ip[j] * FF) + half;
            #pragma unroll
            for (int c = 0; c < 8; c++) {
                float4 v = nb[c];
                acc4[c].x += v.x; acc4[c].y += v.y; acc4[c].z += v.z; acc4[c].w += v.w;
            }
        }
        float4* ss4 = (float4*)ss;
        #pragma unroll
        for (int c = 0; c < 8; c++) ss4[r*16 + half + c] = acc4[c];
    }
    __syncthreads();

    const int rg = tid >> 4, cg = (tid & 15) * 4;
    u64 acc2[8][2];
    mm_tile2(ss, Ws, acc2, rg, cg);
    #pragma unroll
    for (int r = 0; r < 8; r++) {
        const size_t row = rowbase + rg*8 + r;
        const float4 hv = *(const float4*)&hin[row*FF + cg];
        const float2 p0 = unpack2(acc2[r][0]);
        const float2 p1 = unpack2(acc2[r][1]);
        float4 o;
        o.x = p0.x + 6.f*bs[cg+0] + hv.x;
        o.y = p0.y + 6.f*bs[cg+1] + hv.y;
        o.z = p1.x + 6.f*bs[cg+2] + hv.z;
        o.w = p1.y + 6.f*bs[cg+3] + hv.w;
        *(float4*)&out[row*FF + cg] = o;
    }
}

// ---------------------------------------------------------------------------
// Fused prelu(.@W3+b3) -> prelu(.@W4+b4) -> per-block column partial sums (pool)
// ---------------------------------------------------------------------------
__global__ void __launch_bounds__(256) lin34_pool_kernel(
    const float* __restrict__ hin,
    const float* __restrict__ W3, const float* __restrict__ b3, const float* __restrict__ a3,
    const float* __restrict__ W4, const float* __restrict__ b4, const float* __restrict__ a4)
{
    extern __shared__ float smf[];
    float* xs = smf;             // 8192
    float* Ws = smf + 8192;      // 8192
    float* ps = smf + 16384;     // 1024
    float* bs = smf + 17408;     // 256
    const int tid = threadIdx.x;
    const size_t rowbase = (size_t)blockIdx.x * 128;

    float4* xs4 = (float4*)xs;
    const float4* xin = (const float4*)(hin + rowbase * FF);
    for (int i = tid; i < 2048; i += 256) xs4[i] = xin[i];
    float4* Ws4 = (float4*)Ws;
    for (int i = tid; i < 1024; i += 256) {
        Ws4[i]        = ((const float4*)W3)[i];
        Ws4[1024 + i] = ((const float4*)W4)[i];
    }
    if (tid < 64) { bs[tid] = b3[tid]; bs[64+tid] = a3[tid]; bs[128+tid] = b4[tid]; bs[192+tid] = a4[tid]; }
    __syncthreads();

    const int rg = tid >> 4, cg = (tid & 15) * 4;
    u64 acc2[8][2];
    mm_tile2(xs, Ws, acc2, rg, cg);
    __syncthreads();
    #pragma unroll
    for (int r = 0; r < 8; r++) {
        const float2 p0 = unpack2(acc2[r][0]);
        const float2 p1 = unpack2(acc2[r][1]);
        const float a4[4] = {p0.x, p0.y, p1.x, p1.y};
        #pragma unroll
        for (int c = 0; c < 4; c++) {
            float v = a4[c] + bs[cg + c];
            v = (v >= 0.f) ? v : v * bs[64 + cg + c];
            xs[(rg*8 + r)*64 + cg + c] = v;
        }
    }
    __syncthreads();
    mm_tile2(xs, Ws + 4096, acc2, rg, cg);

    float cs[4] = {0.f, 0.f, 0.f, 0.f};
    #pragma unroll
    for (int r = 0; r < 8; r++) {
        const float2 p0 = unpack2(acc2[r][0]);
        const float2 p1 = unpack2(acc2[r][1]);
        const float a4[4] = {p0.x, p0.y, p1.x, p1.y};
        #pragma unroll
        for (int c = 0; c < 4; c++) {
            float v = a4[c] + bs[128 + cg + c];
            v = (v >= 0.f) ? v : v * bs[192 + cg + c];
            cs[c] += v;
        }
    }
    #pragma unroll
    for (int c = 0; c < 4; c++) ps[rg*64 + cg + c] = cs[c];
    __syncthreads();

    if (tid < 64) {
        float s = 0.f;
        #pragma unroll
        for (int i = 0; i < 16; i++) s += ps[i*64 + tid];
        g_part[(size_t)blockIdx.x * FF + tid] = s;
    }
}

// ---------------------------------------------------------------------------
// Head MLP: pooled[64] -> 256 -> 256 -> 64 -> 1 (leaky 0.2). One block per graph.
// ---------------------------------------------------------------------------
__global__ void __launch_bounds__(256) head_kernel(
    const float* __restrict__ Wh1, const float* __restrict__ bh1,
    const float* __restrict__ Wh2, const float* __restrict__ bh2,
    const float* __restrict__ Wh3, const float* __restrict__ bh3,
    const float* __restrict__ Wh4, const float* __restrict__ bh4,
    float* __restrict__ out)
{
    __shared__ float p[64], y1[256], y2[256], y3[64];
    const int g = blockIdx.x, t = threadIdx.x;
    if (t < 64) {
        p[t] = g_part[(size_t)(g*4 + 0)*FF + t] + g_part[(size_t)(g*4 + 1)*FF + t]
             + g_part[(size_t)(g*4 + 2)*FF + t] + g_part[(size_t)(g*4 + 3)*FF + t];
    }
    __syncthreads();
    {
        float v = bh1[t];
        #pragma unroll 4
        for (int k = 0; k < 64; k++) v = fmaf(p[k], Wh1[k*256 + t], v);
        y1[t] = (v >= 0.f) ? v : 0.2f * v;
    }
    __syncthreads();
    {
        float v = bh2[t];
        #pragma unroll 4
        for (int k = 0; k < 256; k++) v = fmaf(y1[k], Wh2[k*256 + t], v);
        y2[t] = (v >= 0.f) ? v : 0.2f * v;
    }
    __syncthreads();
    if (t < 64) {
        float v = bh3[t];
        #pragma unroll 4
        for (int k = 0; k < 256; k++) v = fmaf(y2[k], Wh3[k*64 + t], v);
        y3[t] = (v >= 0.f) ? v : 0.2f * v;
    }
    __syncthreads();
    if (t == 0) {
        float v = bh4[0];
        #pragma unroll
        for (int k = 0; k < 64; k++) v = fmaf(y3[k], Wh4[k], v);
        out[g] = v;
    }
}

// ---------------------------------------------------------------------------
extern "C" void kernel_launch(void* const* d_in, const int* in_sizes, int n_in,
                              void* d_out, int out_size)
{
    const float* x   = (const float*)d_in[0];
    const float* W1  = (const float*)d_in[1];
    const float* b1  = (const float*)d_in[2];
    const float* a1  = (const float*)d_in[3];
    const float* W2  = (const float*)d_in[4];
    const float* b2  = (const float*)d_in[5];
    const float* a2  = (const float*)d_in[6];
    const float* Wc1 = (const float*)d_in[7];
    const float* bc1 = (const float*)d_in[8];
    const float* Wc2 = (const float*)d_in[9];
    const float* bc2 = (const float*)d_in[10];
    const float* Wc3 = (const float*)d_in[11];
    const float* bc3 = (const float*)d_in[12];
    const float* Wc4 = (const float*)d_in[13];
    const float* bc4 = (const float*)d_in[14];
    const float* W3  = (const float*)d_in[15];
    const float* b3  = (const float*)d_in[16];
    const float* a3  = (const float*)d_in[17];
    const float* W4  = (const float*)d_in[18];
    const float* b4  = (const float*)d_in[19];
    const float* a4  = (const float*)d_in[20];
    const float* Wh1 = (const float*)d_in[21];
    const float* bh1 = (const float*)d_in[22];
    const float* Wh2 = (const float*)d_in[23];
    const float* bh2 = (const float*)d_in[24];
    const float* Wh3 = (const float*)d_in[25];
    const float* bh3 = (const float*)d_in[26];
    const float* Wh4 = (const float*)d_in[27];
    const float* bh4 = (const float*)d_in[28];
    float* out = (float*)d_out;

    float *hA = nullptr, *hB = nullptr;
    cudaGetSymbolAddress((void**)&hA, g_hA);
    cudaGetSymbolAddress((void**)&hB, g_hB);

    cudaFuncSetAttribute(knn_kernel,       cudaFuncAttributeMaxDynamicSharedMemorySize, KNN_SMEM);
    cudaFuncSetAttribute(lin12_kernel,     cudaFuncAttributeMaxDynamicSharedMemorySize, LIN12_SMEM);
    cudaFuncSetAttribute(gconv_kernel,     cudaFuncAttributeMaxDynamicSharedMemorySize, GCONV_SMEM);
    cudaFuncSetAttribute(lin34_pool_kernel,cudaFuncAttributeMaxDynamicSharedMemorySize, LIN34_SMEM);

    knn_kernel<<<GG, 256, KNN_SMEM>>>(x);
    lin12_kernel<<<TT/128, 256, LIN12_SMEM>>>(x, W1, b1, a1, W2, b2, a2, hA);
    gconv_kernel<<<TT/128, 256, GCONV_SMEM>>>(hA, Wc1, bc1, hB);
    gconv_kernel<<<TT/128, 256, GCONV_SMEM>>>(hB, Wc2, bc2, hA);
    gconv_kernel<<<TT/128, 256, GCONV_SMEM>>>(hA, Wc3, bc3, hB);
    gconv_kernel<<<TT/128, 256, GCONV_SMEM>>>(hB, Wc4, bc4, hA);
    lin34_pool_kernel<<<TT/128, 256, LIN34_SMEM>>>(hA, W3, b3, a3, W4, b4, a4);
    head_kernel<<<GG, 256>>>(Wh1, bh1, Wh2, bh2, Wh3, bh3, Wh4, bh4, out);
}